// round 2
// baseline (speedup 1.0000x reference)
#include <cuda_runtime.h>
#include <mma.h>
#include <cstdint>
#include <cstddef>

using namespace nvcuda;

#define NN 10000
#define NE 320000
#define FD 256
#define EDF 64

// ---------------- scratch (device globals: no allocation allowed) ----------------
__device__ float g_h0[NN * FD];
__device__ float g_h1[NN * FD];
__device__ float g_Xs[NN * FD];
__device__ float g_Xd[NN * FD];
__device__ float g_EF[(size_t)NE * FD];
__device__ int g_rowptr[NN + 1];
__device__ int g_cnt[NN];
__device__ int g_ofs[NN];
__device__ int g_srcs[NE];
__device__ int g_eids[NE];

// ---------------- helpers ----------------
__device__ __forceinline__ float gelu_f(float v) {
    // JAX gelu(approximate=True): 0.5*v*(1+tanh(sqrt(2/pi)*(v+0.044715 v^3)))
    float u = 0.7978845608028654f * (v + 0.044715f * v * v * v);
    float t;
    asm("tanh.approx.f32 %0, %1;" : "=f"(t) : "f"(u));
    return 0.5f * v * (1.0f + t);
}

// ---------------- CSR construction (sort edges by dst, no fp atomics on hot path) ----------------
__global__ void zero_kernel(int* __restrict__ p, int n) {
    int i = blockIdx.x * blockDim.x + threadIdx.x;
    if (i < n) p[i] = 0;
}

// edge_index is int32 on device (JAX x64 disabled): ei[0:E]=src, ei[E:2E]=dst
__global__ void hist_kernel(const int* __restrict__ ei, int* __restrict__ cnt, int E) {
    int e = blockIdx.x * blockDim.x + threadIdx.x;
    if (e < E) atomicAdd(&cnt[ei[E + e]], 1);
}

// single block, 1024 threads, handles up to 16384 segments
__global__ void scan_kernel(const int* __restrict__ cnt, int* __restrict__ rowptr,
                            int* __restrict__ ofs, int n) {
    __shared__ int part[1024];
    const int PER = 16;
    int t = threadIdx.x;
    int base = t * PER;
    int local[PER];
    int s = 0;
#pragma unroll
    for (int j = 0; j < PER; j++) {
        int idx = base + j;
        int c = (idx < n) ? cnt[idx] : 0;
        local[j] = s;
        s += c;
    }
    part[t] = s;
    __syncthreads();
    for (int off = 1; off < 1024; off <<= 1) {
        int v = (t >= off) ? part[t - off] : 0;
        __syncthreads();
        part[t] += v;
        __syncthreads();
    }
    int pre = (t > 0) ? part[t - 1] : 0;
#pragma unroll
    for (int j = 0; j < PER; j++) {
        int idx = base + j;
        if (idx < n) {
            int v = pre + local[j];
            rowptr[idx] = v;
            ofs[idx] = v;
        }
    }
    if (t == 1023) rowptr[n] = part[1023];
}

__global__ void scatter_kernel(const int* __restrict__ ei, int* __restrict__ ofs,
                               int* __restrict__ srcs, int* __restrict__ eids, int E) {
    int e = blockIdx.x * blockDim.x + threadIdx.x;
    if (e < E) {
        int d = ei[E + e];
        int p = atomicAdd(&ofs[d], 1);
        srcs[p] = ei[e];
        eids[p] = e;
    }
}

// ---------------- tf32 GEMM: C = op(A@B + bias [+resid]), fp32 in/out ----------------
// A: [M,K] row-major (lda), B: [K,Nn] row-major slice (ldb), C/resid: [M,Nn] (ld = Nn)
__global__ void __launch_bounds__(256) gemm_tf32(
    const float* __restrict__ A, int lda,
    const float* __restrict__ B, int ldb,
    const float* __restrict__ bias,
    const float* __restrict__ resid,
    float* __restrict__ C,
    int M, int Nn, int K, int dogelu)
{
    constexpr int BM = 128, BN = 64, BK = 32;
    constexpr int LDA_S = BK + 4;  // 36 (mult of 4 -> 16B row alignment holds)
    constexpr int LDB_S = BN + 4;  // 68
    __shared__ __align__(16) unsigned char smem_raw[BM * BN * 4];  // 32 KB, reused for C
    float* As = (float*)smem_raw;
    float* Bs = As + BM * LDA_S;  // 18432B + 8704B = 27136B <= 32768B
    float* Cs = (float*)smem_raw;

    int tid = threadIdx.x;
    int warp = tid >> 5;
    int wm = warp >> 1, wn = warp & 1;  // 4x2 warp grid, each warp 32x32
    int bm = blockIdx.x * BM, bn = blockIdx.y * BN;

    wmma::fragment<wmma::accumulator, 16, 16, 8, float> acc[2][2];
#pragma unroll
    for (int i = 0; i < 2; i++)
#pragma unroll
        for (int j = 0; j < 2; j++) wmma::fill_fragment(acc[i][j], 0.0f);

    for (int k0 = 0; k0 < K; k0 += BK) {
        __syncthreads();
        {  // A tile: 128x32 floats
            int r = tid >> 3, cg = (tid & 7) << 2;
#pragma unroll
            for (int p = 0; p < 4; p++) {
                int row = r + p * 32;
                int grow = bm + row;
                float4 v = make_float4(0.f, 0.f, 0.f, 0.f);
                if (grow < M) v = *(const float4*)(A + (size_t)grow * lda + k0 + cg);
                *(float4*)(As + row * LDA_S + cg) = v;
            }
        }
        {  // B tile: 32x64 floats
            int r = tid >> 4, cg = (tid & 15) << 2;
#pragma unroll
            for (int p = 0; p < 2; p++) {
                int row = r + p * 16;
                float4 v = *(const float4*)(B + (size_t)(k0 + row) * ldb + bn + cg);
                *(float4*)(Bs + row * LDB_S + cg) = v;
            }
        }
        __syncthreads();
#pragma unroll
        for (int kk = 0; kk < BK; kk += 8) {
            wmma::fragment<wmma::matrix_a, 16, 16, 8, wmma::precision::tf32, wmma::row_major> a[2];
            wmma::fragment<wmma::matrix_b, 16, 16, 8, wmma::precision::tf32, wmma::row_major> b[2];
#pragma unroll
            for (int i = 0; i < 2; i++) {
                wmma::load_matrix_sync(a[i], As + (wm * 32 + i * 16) * LDA_S + kk, LDA_S);
#pragma unroll
                for (int e = 0; e < a[i].num_elements; e++)
                    a[i].x[e] = wmma::__float_to_tf32(a[i].x[e]);
            }
#pragma unroll
            for (int j = 0; j < 2; j++) {
                wmma::load_matrix_sync(b[j], Bs + kk * LDB_S + wn * 32 + j * 16, LDB_S);
#pragma unroll
                for (int e = 0; e < b[j].num_elements; e++)
                    b[j].x[e] = wmma::__float_to_tf32(b[j].x[e]);
            }
#pragma unroll
            for (int i = 0; i < 2; i++)
#pragma unroll
                for (int j = 0; j < 2; j++)
                    wmma::mma_sync(acc[i][j], a[i], b[j], acc[i][j]);
        }
    }
    __syncthreads();
#pragma unroll
    for (int i = 0; i < 2; i++)
#pragma unroll
        for (int j = 0; j < 2; j++)
            wmma::store_matrix_sync(Cs + (wm * 32 + i * 16) * BN + wn * 32 + j * 16,
                                    acc[i][j], BN, wmma::mem_row_major);
    __syncthreads();
    for (int idx = tid; idx < BM * BN; idx += 256) {
        int r = idx >> 6, c = idx & 63;
        int grow = bm + r;
        if (grow >= M) continue;
        float v = Cs[idx];
        if (bias) v += bias[bn + c];
        if (dogelu) v = gelu_f(v);
        if (resid) v += resid[(size_t)grow * Nn + bn + c];
        C[(size_t)grow * Nn + bn + c] = v;
    }
}

// ---------------- edge aggregation: per-dst register accumulation, no atomics ----------------
// 4 nodes per 256-thread block; 64 threads per node, each owning 4 contiguous columns (float4)
__global__ void __launch_bounds__(256) edge_kernel(
    const float* __restrict__ Xs, const float* __restrict__ Xd,
    const float* __restrict__ EF, const float* __restrict__ hin,
    float* __restrict__ hout, int Nn)
{
    int node = blockIdx.x * 4 + (threadIdx.x >> 6);
    if (node >= Nn) return;
    int q = threadIdx.x & 63;
    const float4* Xs4 = (const float4*)Xs;
    const float4* EF4 = (const float4*)EF;
    float4 xd = ((const float4*)Xd)[(size_t)node * 64 + q];
    float4 acc = make_float4(0.f, 0.f, 0.f, 0.f);
    int beg = g_rowptr[node], end = g_rowptr[node + 1];
    for (int i = beg; i < end; i++) {
        int s = g_srcs[i];
        int e = g_eids[i];
        float4 a = Xs4[(size_t)s * 64 + q];
        float4 f = EF4[(size_t)e * 64 + q];
        acc.x += gelu_f(a.x + xd.x + f.x);
        acc.y += gelu_f(a.y + xd.y + f.y);
        acc.z += gelu_f(a.z + xd.z + f.z);
        acc.w += gelu_f(a.w + xd.w + f.w);
    }
    float4 h = ((const float4*)hin)[(size_t)node * 64 + q];
    h.x += acc.x; h.y += acc.y; h.z += acc.z; h.w += acc.w;
    ((float4*)hout)[(size_t)node * 64 + q] = h;
}

// ---------------- launch ----------------
extern "C" void kernel_launch(void* const* d_in, const int* in_sizes, int n_in,
                              void* d_out, int out_size) {
    const float* x    = (const float*)d_in[0];
    const int* ei     = (const int*)d_in[1];   // int32: JAX x64 is disabled
    const float* ef   = (const float*)d_in[2];
    const float* Wff1 = (const float*)d_in[3];
    const float* bff1 = (const float*)d_in[4];
    const float* Wmp1 = (const float*)d_in[5];
    const float* bmp1 = (const float*)d_in[6];
    const float* Wmp2 = (const float*)d_in[7];
    const float* bmp2 = (const float*)d_in[8];
    const float* Wff2 = (const float*)d_in[9];
    const float* bff2 = (const float*)d_in[10];

    int N = in_sizes[0] / FD;
    int E = in_sizes[1] / 2;

    float *h0, *h1, *Xs, *Xd, *EF;
    int *rowptr, *cnt, *ofs, *srcs, *eids;
    cudaGetSymbolAddress((void**)&h0, g_h0);
    cudaGetSymbolAddress((void**)&h1, g_h1);
    cudaGetSymbolAddress((void**)&Xs, g_Xs);
    cudaGetSymbolAddress((void**)&Xd, g_Xd);
    cudaGetSymbolAddress((void**)&EF, g_EF);
    cudaGetSymbolAddress((void**)&rowptr, g_rowptr);
    cudaGetSymbolAddress((void**)&cnt, g_cnt);
    cudaGetSymbolAddress((void**)&ofs, g_ofs);
    cudaGetSymbolAddress((void**)&srcs, g_srcs);
    cudaGetSymbolAddress((void**)&eids, g_eids);

    dim3 thr(256);
    int eb = (E + 255) / 256;

    // CSR by dst
    zero_kernel<<<(N + 255) / 256, thr>>>(cnt, N);
    hist_kernel<<<eb, thr>>>(ei, cnt, E);
    scan_kernel<<<1, 1024>>>(cnt, rowptr, ofs, N);
    scatter_kernel<<<eb, thr>>>(ei, ofs, srcs, eids, E);

    dim3 gN((N + 127) / 128, FD / 64);
    dim3 gE((E + 127) / 128, FD / 64);

    // FFN1: h0 = gelu(x @ W_ff1 + b_ff1)
    gemm_tf32<<<gN, thr>>>(x, FD, Wff1, FD, bff1, nullptr, h0, N, FD, FD, 1);

    // MP layer 1 (W_mp1 rows: [0:256]=src, [256:512]=dst, [512:576]=edge)
    gemm_tf32<<<gN, thr>>>(h0, FD, Wmp1, FD, nullptr, nullptr, Xs, N, FD, FD, 0);
    gemm_tf32<<<gN, thr>>>(h0, FD, Wmp1 + FD * FD, FD, nullptr, nullptr, Xd, N, FD, FD, 0);
    gemm_tf32<<<gE, thr>>>(ef, EDF, Wmp1 + 2 * FD * FD, FD, bmp1, nullptr, EF, E, FD, EDF, 0);
    edge_kernel<<<(N + 3) / 4, thr>>>(Xs, Xd, EF, h0, h1, N);

    // MP layer 2
    gemm_tf32<<<gN, thr>>>(h1, FD, Wmp2, FD, nullptr, nullptr, Xs, N, FD, FD, 0);
    gemm_tf32<<<gN, thr>>>(h1, FD, Wmp2 + FD * FD, FD, nullptr, nullptr, Xd, N, FD, FD, 0);
    gemm_tf32<<<gE, thr>>>(ef, EDF, Wmp2 + 2 * FD * FD, FD, bmp2, nullptr, EF, E, FD, EDF, 0);
    edge_kernel<<<(N + 3) / 4, thr>>>(Xs, Xd, EF, h1, h0, N);

    // FFN2 + residual: out = x + h0 @ W_ff2 + b_ff2
    gemm_tf32<<<gN, thr>>>(h0, FD, Wff2, FD, bff2, x, (float*)d_out, N, FD, FD, 0);
}